// round 14
// baseline (speedup 1.0000x reference)
#include <cuda_runtime.h>

// Fixed problem shape: B=1, T=4, V=6, H=128, W=128
#define MAXID    8192
#define BT       4
#define M_ELEMS  393216
#define VHW      (M_ELEMS / BT)       // 98304
#define NSEGS    (BT * MAXID)         // 32768
#define REC      112                  // per-segment record (floats), 448B
#define THRF     2.0f
#define DUPF     0.05f
#define FULL     0xffffffffu
#define NE       64                   // elements per k_out block

// Record layout (float slots):
//  [0..63] dense  [64..79] inst  [80..87] motion  [88..91] rot
//  [92..94] center [95..97] offset [98] opacity [99..101] scale
//  [102..104] feat_dc [105] dyn [106] d2 (sum e2) [107..111] pad

struct Meta {
    int                cnt[NSEGS];
    unsigned long long rep[NSEGS];   // packed (ordered(k)<<32 | ~i)
    float4             e1c[NSEGS];   // {d1, sum(cen*e1).xyz}
};
__device__ Meta          g_meta;
__device__ unsigned char g_act[M_ELEMS];
__device__ __align__(16) float g_sums[(size_t)NSEGS * REC];

__device__ __forceinline__ void red4(float* addr, float a, float b, float c, float d) {
    asm volatile("red.global.add.v4.f32 [%0], {%1,%2,%3,%4};"
                 :: "l"(addr), "f"(a), "f"(b), "f"(c), "f"(d) : "memory");
}

// ---------------- Pass 1: count + e1/cen*e1 accumulate (4 elems/thread) ----
__global__ void k_p12(const int* __restrict__ ids, const float* __restrict__ kp,
                      const float* __restrict__ cen) {
    int base = (blockIdx.x * blockDim.x + threadIdx.x) * 4;
    if (base >= M_ELEMS) return;
    int4   id4 = *(const int4*)(ids + base);
    float4 k4  = *(const float4*)(kp + base);
    float4 c0 = *(const float4*)(cen + (size_t)base * 3);
    float4 c1 = *(const float4*)(cen + (size_t)base * 3 + 4);
    float4 c2 = *(const float4*)(cen + (size_t)base * 3 + 8);
    int bt = base / VHW;   // VHW % 4 == 0, no straddle

    int   idv[4] = {id4.x, id4.y, id4.z, id4.w};
    float kv[4]  = {k4.x, k4.y, k4.z, k4.w};
    float cx[4] = {c0.x, c0.w, c1.z, c2.y};
    float cy[4] = {c0.y, c1.x, c1.w, c2.z};
    float cz[4] = {c0.z, c1.y, c2.x, c2.w};
#pragma unroll
    for (int j = 0; j < 4; j++) {
        if (idv[j] >= 0) {
            int seg = bt * MAXID + idv[j];
            float e1 = expf(kv[j]);
            atomicAdd(&g_meta.cnt[seg], 1);
            red4((float*)&g_meta.e1c[seg], e1, cx[j] * e1, cy[j] * e1, cz[j] * e1);
        }
    }
}

// ------- Pass 2: act + rep + ALL weighted accumulates in one warp loop -----
__global__ void k_p34(const float* __restrict__ dense, const float* __restrict__ cen,
                      const float* __restrict__ off,   const float* __restrict__ opa,
                      const float* __restrict__ sca,   const float* __restrict__ rot,
                      const float* __restrict__ fdc,   const float* __restrict__ kp,
                      const float* __restrict__ inst,  const float* __restrict__ mot,
                      const float* __restrict__ dyn,   const int* __restrict__ ids) {
    int i = blockIdx.x * blockDim.x + threadIdx.x;
    int lane = threadIdx.x & 31;
    int i0 = i - lane;

    int id = ids[i];
    bool act = false;
    int seg = 0;
    float k0 = 0.f, e2 = 0.f;
    if (id >= 0) {
        seg = (i / VHW) * MAXID + id;
        if (__ldg(&g_meta.cnt[seg]) >= 2) {
            float4 f = __ldg(&g_meta.e1c[seg]);
            float inv = (f.x > 0.0f) ? (1.0f / f.x) : 1.0f;
            float dx = cen[3 * (size_t)i + 0] - f.y * inv;
            float dy = cen[3 * (size_t)i + 1] - f.z * inv;
            float dz = cen[3 * (size_t)i + 2] - f.w * inv;
            float dist = sqrtf(dx * dx + dy * dy + dz * dz);
            if (dist <= THRF) { act = true; k0 = kp[i]; }
        }
    }
    g_act[i] = act ? 1 : 0;

    if (act) {
        unsigned kb  = __float_as_uint(k0);
        unsigned ord = (k0 >= 0.0f) ? (kb | 0x80000000u) : ~kb;
        atomicMax(&g_meta.rep[seg], ((unsigned long long)ord << 32) | (FULL - (unsigned)i));
        e2 = expf(k0);
    }

    // hoisted per-lane source map (vector channels, lanes 0..22)
    const float4* vp = (const float4*)rot;
    int vs = 1;
    if (lane < 16)      { vp = (const float4*)dense + lane;       vs = 16; }
    else if (lane < 20) { vp = (const float4*)inst + (lane - 16); vs = 4;  }
    else if (lane < 22) { vp = (const float4*)mot + (lane - 20);  vs = 2;  }

    unsigned m = __ballot_sync(FULL, act);
#pragma unroll 4
    for (int j = 0; j < 32; j++) {
        if (!((m >> j) & 1)) continue;
        int   e  = i0 + j;
        int   sg = __shfl_sync(FULL, seg, j);
        float w  = __shfl_sync(FULL, e2, j);
        float* base = g_sums + (size_t)sg * REC;
        if (lane < 23) {
            float4 v = __ldcs(vp + (size_t)e * vs);
            red4(base + lane * 4, v.x * w, v.y * w, v.z * w, v.w * w);
        } else if (lane == 23) {           // slots 92..95: cen xyz, off0
            float a = __ldg(cen + 3 * (size_t)e);
            float b = __ldg(cen + 3 * (size_t)e + 1);
            float c = __ldg(cen + 3 * (size_t)e + 2);
            float d = __ldg(off + 3 * (size_t)e);
            red4(base + 92, a * w, b * w, c * w, d * w);
        } else if (lane == 24) {           // slots 96..99: off12, opa, sca0
            float a = __ldg(off + 3 * (size_t)e + 1);
            float b = __ldg(off + 3 * (size_t)e + 2);
            float c = __ldg(opa + e);
            float d = __ldg(sca + 3 * (size_t)e);
            red4(base + 96, a * w, b * w, c * w, d * w);
        } else if (lane == 25) {           // slots 100..103: sca12, fdc01
            float a = __ldg(sca + 3 * (size_t)e + 1);
            float b = __ldg(sca + 3 * (size_t)e + 2);
            float c = __ldg(fdc + 3 * (size_t)e);
            float d = __ldg(fdc + 3 * (size_t)e + 1);
            red4(base + 100, a * w, b * w, c * w, d * w);
        } else if (lane == 26) {           // slots 104..106: fdc2, dyn, d2
            float a = __ldg(fdc + 3 * (size_t)e + 2);
            float b = __ldg(dyn + e);
            red4(base + 104, a * w, b * w, w, 0.0f);
        }
    }
}

// -------- Pass 3: block-staged output with active/inactive compaction ------
__global__ __launch_bounds__(256) void k_out(
        const float* __restrict__ dense, const float* __restrict__ cen,
        const float* __restrict__ off,   const float* __restrict__ opa,
        const float* __restrict__ sca,   const float* __restrict__ rot,
        const float* __restrict__ fdc,   const float* __restrict__ kp,
        const float* __restrict__ inst,  const float* __restrict__ mot,
        const float* __restrict__ dyn,   const int* __restrict__ ids,
        float* __restrict__ out) {
    __shared__ __align__(16) float rec[NE][REC];   // slot-indexed
    __shared__ int   perm[NE];                     // slot -> element
    __shared__ int   iperm[NE];                    // element -> slot
    __shared__ int   pseg[NE];                     // slot -> segment (active)
    __shared__ unsigned char sact[NE];             // element-indexed
    __shared__ float einv[NE], efac[NE], emx2[NE]; // element-indexed
    __shared__ int   cnt_a, cnt_i;

    int base = blockIdx.x * NE;
    int t = threadIdx.x;
    if (t == 0) { cnt_a = 0; cnt_i = 0; }
    __syncthreads();

    if (t < NE) {
        int i = base + t;
        int a = __ldg(&g_act[i]);
        sact[t] = (unsigned char)a;
        int slot;
        if (a) {
            slot = atomicAdd(&cnt_a, 1);
            pseg[slot] = 0;
        } else {
            slot = NE - 1 - atomicAdd(&cnt_i, 1);
        }
        perm[slot] = t;
        iperm[t] = slot;
        if (a) pseg[slot] = (i / VHW) * MAXID + __ldg(&ids[i]);
    }
    __syncthreads();
    int nact = cnt_a;

    // stage records for active slots (L2-resident reads)
#pragma unroll
    for (int it = 0; it < 7; it++) {
        int j = it * 256 + t;
        int p = j / 28, q = j - p * 28;
        if (p < nact)
            ((float4*)rec[p])[q] =
                __ldg((const float4*)(g_sums + (size_t)pseg[p] * REC) + q);
    }
    __syncthreads();

    if (t < nact) {
        int e = perm[t];
        einv[e] = 1.0f / rec[t][106];
        unsigned long long pk = __ldg(&g_meta.rep[pseg[t]]);
        unsigned ou = (unsigned)(pk >> 32);
        emx2[e] = (ou & 0x80000000u) ? __uint_as_float(ou & 0x7FFFFFFFu)
                                     : __uint_as_float(~ou);
        unsigned rep_i = FULL - (unsigned)(pk & FULL);
        efac[e] = ((unsigned)(base + e) == rep_i) ? 1.0f : DUPF;
    }
    __syncthreads();

    const size_t M = M_ELEMS;
    float* o_dense = out;
    float* o_cen   = out + 64 * M;
    float* o_off   = out + 67 * M;
    float* o_opa   = out + 70 * M;
    float* o_sca   = out + 71 * M;
    float* o_rot   = out + 74 * M;
    float* o_fdc   = out + 78 * M;
    float* o_kp    = out + 81 * M;
    float* o_inst  = out + 82 * M;
    float* o_mot   = out + 98 * M;
    float* o_dyn   = out + 106 * M;

    // dense: slot-ordered -> uniform warps; streaming loads/stores
    {
        const float4* in4 = (const float4*)dense;
        float4* out4 = (float4*)o_dense;
#pragma unroll
        for (int it = 0; it < 4; it++) {
            int j = it * 256 + t;
            int slot = j >> 4, q = j & 15;
            int e = perm[slot];
            size_t g = (size_t)(base + e) * 16 + q;
            float4 v;
            if (slot < nact) {
                float iv = einv[e];
                float4 r = ((const float4*)rec[slot])[q];
                v = make_float4(r.x * iv, r.y * iv, r.z * iv, r.w * iv);
            } else {
                v = __ldcs(in4 + g);
            }
            __stcs(out4 + g, v);
        }
    }
    // inst
    {
        int slot = t >> 2, q = t & 3;
        int e = perm[slot];
        size_t g = (size_t)(base + e) * 4 + q;
        float4 v;
        if (slot < nact) {
            float iv = einv[e];
            float4 r = ((const float4*)rec[slot])[16 + q];
            v = make_float4(r.x * iv, r.y * iv, r.z * iv, r.w * iv);
        } else {
            v = __ldcs((const float4*)inst + g);
        }
        __stcs((float4*)o_inst + g, v);
    }
    // motion
    if (t < 128) {
        int slot = t >> 1, q = t & 1;
        int e = perm[slot];
        size_t g = (size_t)(base + e) * 2 + q;
        float4 v;
        if (slot < nact) {
            float iv = einv[e];
            float4 r = ((const float4*)rec[slot])[20 + q];
            v = make_float4(r.x * iv, r.y * iv, r.z * iv, r.w * iv);
        } else {
            v = __ldcs((const float4*)mot + g);
        }
        __stcs((float4*)o_mot + g, v);
    }
    // rotation (divide + normalize)
    if (t >= 128 && t < 128 + NE) {
        int slot = t - 128;
        int e = perm[slot];
        size_t g = (size_t)(base + e);
        float4 v;
        if (slot < nact) {
            float iv = einv[e];
            float4 r = ((const float4*)rec[slot])[22];
            v = make_float4(r.x * iv, r.y * iv, r.z * iv, r.w * iv);
            float n = sqrtf(v.x * v.x + v.y * v.y + v.z * v.z + v.w * v.w);
            float qi = 1.0f / fmaxf(n, 1e-12f);
            v = make_float4(v.x * qi, v.y * qi, v.z * qi, v.w * qi);
        } else {
            v = __ldcs((const float4*)rot + g);
        }
        __stcs((float4*)o_rot + g, v);
    }
    // scalars (original element order; coalesced)
    if (t < NE * 3) {
        int e = t / 3, c = t - 3 * e;
        size_t g = (size_t)base * 3 + t;
        if (sact[e]) {
            int slot = iperm[e];
            float iv = einv[e];
            __stcs(o_cen + g, rec[slot][92 + c] * iv);
            __stcs(o_off + g, rec[slot][95 + c] * iv);
            __stcs(o_sca + g, rec[slot][99 + c] * iv);
            __stcs(o_fdc + g, rec[slot][102 + c] * iv);
        } else {
            __stcs(o_cen + g, __ldcs(cen + g));
            __stcs(o_off + g, __ldcs(off + g));
            __stcs(o_sca + g, __ldcs(sca + g));
            __stcs(o_fdc + g, __ldcs(fdc + g));
        }
    } else {
        int e = t - NE * 3;
        size_t g = (size_t)base + e;
        if (sact[e]) {
            int slot = iperm[e];
            float iv = einv[e];
            __stcs(o_opa + g, rec[slot][98] * iv * efac[e]);
            __stcs(o_kp + g,  emx2[e] * efac[e]);
            __stcs(o_dyn + g, rec[slot][105] * iv);
        } else {
            __stcs(o_opa + g, __ldcs(opa + g));
            __stcs(o_kp + g,  __ldcs(kp + g));
            __stcs(o_dyn + g, __ldcs(dyn + g));
        }
    }
}

extern "C" void kernel_launch(void* const* d_in, const int* in_sizes, int n_in,
                              void* d_out, int out_size) {
    const float* dense = (const float*)d_in[0];
    const float* cen   = (const float*)d_in[1];
    const float* off   = (const float*)d_in[2];
    const float* opa   = (const float*)d_in[3];
    const float* sca   = (const float*)d_in[4];
    const float* rot   = (const float*)d_in[5];
    const float* fdc   = (const float*)d_in[6];
    const float* kp    = (const float*)d_in[7];
    const float* inst  = (const float*)d_in[8];
    const float* mot   = (const float*)d_in[9];
    const float* dyn   = (const float*)d_in[10];
    const int*   ids   = (const int*)d_in[11];
    float* out = (float*)d_out;

    void *p_meta, *p_sums;
    cudaGetSymbolAddress(&p_meta, g_meta);
    cudaGetSymbolAddress(&p_sums, g_sums);
    cudaMemsetAsync(p_meta, 0, sizeof(Meta));
    cudaMemsetAsync(p_sums, 0, sizeof(float) * (size_t)NSEGS * REC);

    const int TB = 256;
    const int gM = M_ELEMS / TB;
    const int g4 = (M_ELEMS / 4) / TB;
    const int gO = M_ELEMS / NE;

    k_p12<<<g4, TB>>>(ids, kp, cen);
    k_p34<<<gM, TB>>>(dense, cen, off, opa, sca, rot, fdc, kp, inst, mot, dyn, ids);
    k_out<<<gO, TB>>>(dense, cen, off, opa, sca, rot, fdc, kp, inst, mot, dyn, ids, out);
}

// round 15
// speedup vs baseline: 1.2740x; 1.2740x over previous
#include <cuda_runtime.h>

// Fixed problem shape: B=1, T=4, V=6, H=128, W=128
#define MAXID    8192
#define BT       4
#define M_ELEMS  393216
#define VHW      (M_ELEMS / BT)       // 98304
#define NSEGS    (BT * MAXID)         // 32768
#define REC      112                  // per-segment record (floats), 448B
#define THRF     2.0f
#define DUPF     0.05f
#define FULL     0xffffffffu
#define NE       64                   // elements per k_out block

// Record layout (float slots):
//  [0..63] dense  [64..79] inst  [80..87] motion  [88..91] rot
//  [92..94] center [95..97] offset [98] opacity [99..101] scale
//  [102..104] feat_dc [105] dyn [106] d2 (sum e2) [107..111] pad

struct Meta {
    int                cnt[NSEGS];
    unsigned long long rep[NSEGS];   // packed (ordered(k)<<32 | ~i)
    float4             e1c[NSEGS];   // {d1, sum(cen*e1).xyz}
};
__device__ Meta          g_meta;
__device__ unsigned char g_act[M_ELEMS];
__device__ __align__(16) float g_sums[(size_t)NSEGS * REC];

__device__ __forceinline__ void red4(float* addr, float a, float b, float c, float d) {
    asm volatile("red.global.add.v4.f32 [%0], {%1,%2,%3,%4};"
                 :: "l"(addr), "f"(a), "f"(b), "f"(c), "f"(d) : "memory");
}

// ---------------- Pass 1: count + e1/cen*e1 accumulate (4 elems/thread) ----
__global__ void k_p12(const int* __restrict__ ids, const float* __restrict__ kp,
                      const float* __restrict__ cen) {
    int base = (blockIdx.x * blockDim.x + threadIdx.x) * 4;
    if (base >= M_ELEMS) return;
    int4   id4 = *(const int4*)(ids + base);
    float4 k4  = *(const float4*)(kp + base);
    float4 c0 = *(const float4*)(cen + (size_t)base * 3);
    float4 c1 = *(const float4*)(cen + (size_t)base * 3 + 4);
    float4 c2 = *(const float4*)(cen + (size_t)base * 3 + 8);
    int bt = base / VHW;   // VHW % 4 == 0, no straddle

    int   idv[4] = {id4.x, id4.y, id4.z, id4.w};
    float kv[4]  = {k4.x, k4.y, k4.z, k4.w};
    float cx[4] = {c0.x, c0.w, c1.z, c2.y};
    float cy[4] = {c0.y, c1.x, c1.w, c2.z};
    float cz[4] = {c0.z, c1.y, c2.x, c2.w};
#pragma unroll
    for (int j = 0; j < 4; j++) {
        if (idv[j] >= 0) {
            int seg = bt * MAXID + idv[j];
            float e1 = expf(kv[j]);
            atomicAdd(&g_meta.cnt[seg], 1);
            red4((float*)&g_meta.e1c[seg], e1, cx[j] * e1, cy[j] * e1, cz[j] * e1);
        }
    }
}

// ------- Pass 2 (fused): act + rep + warp-cooperative weighted accumulate --
__global__ void k_p34(const float* __restrict__ dense, const float* __restrict__ cen,
                      const float* __restrict__ off,   const float* __restrict__ opa,
                      const float* __restrict__ sca,   const float* __restrict__ rot,
                      const float* __restrict__ fdc,   const float* __restrict__ kp,
                      const float* __restrict__ inst,  const float* __restrict__ mot,
                      const float* __restrict__ dyn,   const int* __restrict__ ids) {
    int i = blockIdx.x * blockDim.x + threadIdx.x;
    int lane = threadIdx.x & 31;
    int i0 = i - lane;

    int id = ids[i];
    bool act = false;
    int seg = 0;
    float k0 = 0.f, e2 = 0.f;
    if (id >= 0) {
        seg = (i / VHW) * MAXID + id;
        if (__ldg(&g_meta.cnt[seg]) >= 2) {
            float4 f = __ldg(&g_meta.e1c[seg]);
            float inv = (f.x > 0.0f) ? (1.0f / f.x) : 1.0f;
            float dx = cen[3 * (size_t)i + 0] - f.y * inv;
            float dy = cen[3 * (size_t)i + 1] - f.z * inv;
            float dz = cen[3 * (size_t)i + 2] - f.w * inv;
            float dist = sqrtf(dx * dx + dy * dy + dz * dz);
            if (dist <= THRF) { act = true; k0 = kp[i]; }
        }
    }
    g_act[i] = act ? 1 : 0;

    if (act) {
        unsigned kb  = __float_as_uint(k0);
        unsigned ord = (k0 >= 0.0f) ? (kb | 0x80000000u) : ~kb;
        atomicMax(&g_meta.rep[seg], ((unsigned long long)ord << 32) | (FULL - (unsigned)i));

        e2 = expf(k0);
        float* base = g_sums + (size_t)seg * REC;
        float c0 = cen[3 * (size_t)i], c1 = cen[3 * (size_t)i + 1], c2 = cen[3 * (size_t)i + 2];
        float o0 = off[3 * (size_t)i], o1 = off[3 * (size_t)i + 1], o2 = off[3 * (size_t)i + 2];
        float op = opa[i];
        float s0 = sca[3 * (size_t)i], s1 = sca[3 * (size_t)i + 1], s2 = sca[3 * (size_t)i + 2];
        float f0 = fdc[3 * (size_t)i], f1 = fdc[3 * (size_t)i + 1], f2 = fdc[3 * (size_t)i + 2];
        float dn = dyn[i];
        red4(base + 92,  c0 * e2, c1 * e2, c2 * e2, o0 * e2);
        red4(base + 96,  o1 * e2, o2 * e2, op * e2, s0 * e2);
        red4(base + 100, s1 * e2, s2 * e2, f0 * e2, f1 * e2);
        red4(base + 104, f2 * e2, dn * e2, e2,      0.0f);
    }

    // hoisted per-lane source map for phase 2
    const float4* vp = (const float4*)rot;
    int vs = 1;
    if (lane < 16)      { vp = (const float4*)dense + lane;       vs = 16; }
    else if (lane < 20) { vp = (const float4*)inst + (lane - 16); vs = 4;  }
    else if (lane < 22) { vp = (const float4*)mot + (lane - 20);  vs = 2;  }

    unsigned m = __ballot_sync(FULL, act);
#pragma unroll 4
    for (int j = 0; j < 32; j++) {
        if (!((m >> j) & 1)) continue;
        int   e  = i0 + j;
        int   sg = __shfl_sync(FULL, seg, j);
        float w  = __shfl_sync(FULL, e2, j);
        if (lane < 23) {
            float4 v = __ldcs(vp + (size_t)e * vs);   // streaming: protect L2 for g_sums
            red4(g_sums + (size_t)sg * REC + lane * 4,
                 v.x * w, v.y * w, v.z * w, v.w * w);
        }
    }
}

// -------- Pass 3: block-staged output with active/inactive compaction ------
__global__ __launch_bounds__(256) void k_out(
        const float* __restrict__ dense, const float* __restrict__ cen,
        const float* __restrict__ off,   const float* __restrict__ opa,
        const float* __restrict__ sca,   const float* __restrict__ rot,
        const float* __restrict__ fdc,   const float* __restrict__ kp,
        const float* __restrict__ inst,  const float* __restrict__ mot,
        const float* __restrict__ dyn,   const int* __restrict__ ids,
        float* __restrict__ out) {
    __shared__ __align__(16) float rec[NE][REC];   // slot-indexed
    __shared__ int   perm[NE];                     // slot -> element
    __shared__ int   iperm[NE];                    // element -> slot
    __shared__ int   pseg[NE];                     // slot -> segment (active)
    __shared__ unsigned char sact[NE];             // element-indexed
    __shared__ float einv[NE], efac[NE], emx2[NE]; // element-indexed
    __shared__ int   cnt_a, cnt_i;

    int base = blockIdx.x * NE;
    int t = threadIdx.x;
    if (t == 0) { cnt_a = 0; cnt_i = 0; }
    __syncthreads();

    if (t < NE) {
        int i = base + t;
        int a = __ldg(&g_act[i]);
        sact[t] = (unsigned char)a;
        int slot;
        if (a) {
            slot = atomicAdd(&cnt_a, 1);
            pseg[slot] = 0;
        } else {
            slot = NE - 1 - atomicAdd(&cnt_i, 1);
        }
        perm[slot] = t;
        iperm[t] = slot;
        if (a) pseg[slot] = (i / VHW) * MAXID + __ldg(&ids[i]);
    }
    __syncthreads();
    int nact = cnt_a;

    // stage records for active slots: 64*28 float4 loads (L2-resident)
#pragma unroll
    for (int it = 0; it < 7; it++) {
        int j = it * 256 + t;
        int p = j / 28, q = j - p * 28;
        if (p < nact)
            ((float4*)rec[p])[q] =
                __ldg((const float4*)(g_sums + (size_t)pseg[p] * REC) + q);
    }
    __syncthreads();

    if (t < nact) {
        int e = perm[t];
        einv[e] = 1.0f / rec[t][106];
        unsigned long long pk = __ldg(&g_meta.rep[pseg[t]]);
        unsigned ou = (unsigned)(pk >> 32);
        emx2[e] = (ou & 0x80000000u) ? __uint_as_float(ou & 0x7FFFFFFFu)
                                     : __uint_as_float(~ou);
        unsigned rep_i = FULL - (unsigned)(pk & FULL);
        efac[e] = ((unsigned)(base + e) == rep_i) ? 1.0f : DUPF;
    }
    __syncthreads();

    const size_t M = M_ELEMS;
    float* o_dense = out;
    float* o_cen   = out + 64 * M;
    float* o_off   = out + 67 * M;
    float* o_opa   = out + 70 * M;
    float* o_sca   = out + 71 * M;
    float* o_rot   = out + 74 * M;
    float* o_fdc   = out + 78 * M;
    float* o_kp    = out + 81 * M;
    float* o_inst  = out + 82 * M;
    float* o_mot   = out + 98 * M;
    float* o_dyn   = out + 106 * M;

    // dense: slot-ordered -> uniform warps; streaming loads/stores
    {
        const float4* in4 = (const float4*)dense;
        float4* out4 = (float4*)o_dense;
#pragma unroll
        for (int it = 0; it < 4; it++) {
            int j = it * 256 + t;
            int slot = j >> 4, q = j & 15;
            int e = perm[slot];
            size_t g = (size_t)(base + e) * 16 + q;
            float4 v;
            if (slot < nact) {
                float iv = einv[e];
                float4 r = ((const float4*)rec[slot])[q];
                v = make_float4(r.x * iv, r.y * iv, r.z * iv, r.w * iv);
            } else {
                v = __ldcs(in4 + g);
            }
            __stcs(out4 + g, v);
        }
    }
    // inst
    {
        int slot = t >> 2, q = t & 3;
        int e = perm[slot];
        size_t g = (size_t)(base + e) * 4 + q;
        float4 v;
        if (slot < nact) {
            float iv = einv[e];
            float4 r = ((const float4*)rec[slot])[16 + q];
            v = make_float4(r.x * iv, r.y * iv, r.z * iv, r.w * iv);
        } else {
            v = __ldcs((const float4*)inst + g);
        }
        __stcs((float4*)o_inst + g, v);
    }
    // motion
    if (t < 128) {
        int slot = t >> 1, q = t & 1;
        int e = perm[slot];
        size_t g = (size_t)(base + e) * 2 + q;
        float4 v;
        if (slot < nact) {
            float iv = einv[e];
            float4 r = ((const float4*)rec[slot])[20 + q];
            v = make_float4(r.x * iv, r.y * iv, r.z * iv, r.w * iv);
        } else {
            v = __ldcs((const float4*)mot + g);
        }
        __stcs((float4*)o_mot + g, v);
    }
    // rotation (divide + normalize)
    if (t >= 128 && t < 128 + NE) {
        int slot = t - 128;
        int e = perm[slot];
        size_t g = (size_t)(base + e);
        float4 v;
        if (slot < nact) {
            float iv = einv[e];
            float4 r = ((const float4*)rec[slot])[22];
            v = make_float4(r.x * iv, r.y * iv, r.z * iv, r.w * iv);
            float n = sqrtf(v.x * v.x + v.y * v.y + v.z * v.z + v.w * v.w);
            float qi = 1.0f / fmaxf(n, 1e-12f);
            v = make_float4(v.x * qi, v.y * qi, v.z * qi, v.w * qi);
        } else {
            v = __ldcs((const float4*)rot + g);
        }
        __stcs((float4*)o_rot + g, v);
    }
    // scalars (original element order; coalesced)
    if (t < NE * 3) {
        int e = t / 3, c = t - 3 * e;
        size_t g = (size_t)base * 3 + t;
        if (sact[e]) {
            int slot = iperm[e];
            float iv = einv[e];
            __stcs(o_cen + g, rec[slot][92 + c] * iv);
            __stcs(o_off + g, rec[slot][95 + c] * iv);
            __stcs(o_sca + g, rec[slot][99 + c] * iv);
            __stcs(o_fdc + g, rec[slot][102 + c] * iv);
        } else {
            __stcs(o_cen + g, __ldcs(cen + g));
            __stcs(o_off + g, __ldcs(off + g));
            __stcs(o_sca + g, __ldcs(sca + g));
            __stcs(o_fdc + g, __ldcs(fdc + g));
        }
    } else {
        int e = t - NE * 3;
        size_t g = (size_t)base + e;
        if (sact[e]) {
            int slot = iperm[e];
            float iv = einv[e];
            __stcs(o_opa + g, rec[slot][98] * iv * efac[e]);
            __stcs(o_kp + g,  emx2[e] * efac[e]);
            __stcs(o_dyn + g, rec[slot][105] * iv);
        } else {
            __stcs(o_opa + g, __ldcs(opa + g));
            __stcs(o_kp + g,  __ldcs(kp + g));
            __stcs(o_dyn + g, __ldcs(dyn + g));
        }
    }
}

extern "C" void kernel_launch(void* const* d_in, const int* in_sizes, int n_in,
                              void* d_out, int out_size) {
    const float* dense = (const float*)d_in[0];
    const float* cen   = (const float*)d_in[1];
    const float* off   = (const float*)d_in[2];
    const float* opa   = (const float*)d_in[3];
    const float* sca   = (const float*)d_in[4];
    const float* rot   = (const float*)d_in[5];
    const float* fdc   = (const float*)d_in[6];
    const float* kp    = (const float*)d_in[7];
    const float* inst  = (const float*)d_in[8];
    const float* mot   = (const float*)d_in[9];
    const float* dyn   = (const float*)d_in[10];
    const int*   ids   = (const int*)d_in[11];
    float* out = (float*)d_out;

    void *p_meta, *p_sums;
    cudaGetSymbolAddress(&p_meta, g_meta);
    cudaGetSymbolAddress(&p_sums, g_sums);
    cudaMemsetAsync(p_meta, 0, sizeof(Meta));
    cudaMemsetAsync(p_sums, 0, sizeof(float) * (size_t)NSEGS * REC);

    const int TB = 256;
    const int gM = M_ELEMS / TB;
    const int g4 = (M_ELEMS / 4) / TB;
    const int gO = M_ELEMS / NE;

    k_p12<<<g4, TB>>>(ids, kp, cen);
    k_p34<<<gM, TB>>>(dense, cen, off, opa, sca, rot, fdc, kp, inst, mot, dyn, ids);
    k_out<<<gO, TB>>>(dense, cen, off, opa, sca, rot, fdc, kp, inst, mot, dyn, ids, out);
}